// round 2
// baseline (speedup 1.0000x reference)
#include <cuda_runtime.h>

#define N_SAMPLES 2048
#define XDIM      768
#define LOWER     40

// h-GEMM tiling
#define MT 32
#define KC 64

// pairwise tiling
#define JT  128                      // j per block (smem tile)
#define IB  256                      // i per block (1 per thread)
#define NJB (N_SAMPLES / JT)         // 16
#define NIB (N_SAMPLES / IB)         // 8
#define NPAIR (NJB * NIB)            // 128
#define NT0B 8

__device__ float g_hx[N_SAMPLES * LOWER];
__device__ float g_hy[N_SAMPLES * LOWER];
__device__ float g_part_t0[NT0B];
__device__ float g_part_exp[NPAIR];

// ---------------------------------------------------------------------------
// Kernel A: hx = x @ W1[:, :768]^T  and  hy = y @ W1[:, 768:]^T
// grid = (2048/MT, 2), block = 128. Each thread: 2 rows x 5 units.
// ---------------------------------------------------------------------------
__global__ __launch_bounds__(128) void h_gemm(const float* __restrict__ Xin,
                                              const float* __restrict__ Yin,
                                              const float* __restrict__ W1) {
    __shared__ float xs[MT][KC + 1];      // +1 pad: kills 4-way bank conflict
    __shared__ float ws[LOWER][KC + 1];   // +1 pad: kills 8-way bank conflict

    const float* X = blockIdx.y ? Yin : Xin;
    float* H       = blockIdx.y ? g_hy : g_hx;
    const int coloff = blockIdx.y ? XDIM : 0;

    const int tid  = threadIdx.x;
    const int row0 = blockIdx.x * MT;
    const int uu   = tid & 7;    // unit group: units [uu*5, uu*5+5)
    const int rr   = tid >> 3;   // 0..15 -> rows rr and rr+16

    float acc0[5] = {0.f, 0.f, 0.f, 0.f, 0.f};
    float acc1[5] = {0.f, 0.f, 0.f, 0.f, 0.f};

    for (int k0 = 0; k0 < XDIM; k0 += KC) {
        #pragma unroll
        for (int idx = tid; idx < MT * KC; idx += 128) {
            int r = idx >> 6, kk = idx & (KC - 1);
            xs[r][kk] = X[(row0 + r) * XDIM + k0 + kk];
        }
        #pragma unroll
        for (int idx = tid; idx < LOWER * KC; idx += 128) {
            int u = idx >> 6, kk = idx & (KC - 1);
            ws[u][kk] = W1[u * (2 * XDIM) + coloff + k0 + kk];
        }
        __syncthreads();

        #pragma unroll 4
        for (int kk = 0; kk < KC; kk++) {
            float x0 = xs[rr][kk];
            float x1 = xs[rr + 16][kk];
            #pragma unroll
            for (int jj = 0; jj < 5; jj++) {
                float w = ws[uu * 5 + jj][kk];
                acc0[jj] = fmaf(x0, w, acc0[jj]);
                acc1[jj] = fmaf(x1, w, acc1[jj]);
            }
        }
        __syncthreads();
    }

    #pragma unroll
    for (int jj = 0; jj < 5; jj++) {
        H[(row0 + rr) * LOWER + uu * 5 + jj]        = acc0[jj];
        H[(row0 + rr + 16) * LOWER + uu * 5 + jj]   = acc1[jj];
    }
}

// ---------------------------------------------------------------------------
// Kernel B: T0 diagonal term. Sum_i [ W2 . relu(hx_i + hy_i + b1) + b2 ]
// ---------------------------------------------------------------------------
__global__ __launch_bounds__(256) void t0_kernel(const float* __restrict__ b1,
                                                 const float* __restrict__ W2,
                                                 const float* __restrict__ b2) {
    __shared__ float red[256];
    int i = blockIdx.x * 256 + threadIdx.x;
    float t = b2[0];
    #pragma unroll
    for (int u = 0; u < LOWER; u++)
        t = fmaf(W2[u], fmaxf(g_hx[i * LOWER + u] + g_hy[i * LOWER + u] + b1[u], 0.f), t);
    red[threadIdx.x] = t;
    __syncthreads();
    for (int s = 128; s > 0; s >>= 1) {
        if (threadIdx.x < s) red[threadIdx.x] += red[threadIdx.x + s];
        __syncthreads();
    }
    if (threadIdx.x == 0) g_part_t0[blockIdx.x] = red[0];
}

// ---------------------------------------------------------------------------
// Kernel C: pairwise Sum_{i,j} exp( W2 . relu(hy_i + b1 + hx_j) + b2 - 1 )
// grid = (NJB, NIB), block = 256 (one i per thread). hx j-tile in smem:
// all threads read the same (j,u) -> pure broadcast, conflict-free.
// ---------------------------------------------------------------------------
__global__ __launch_bounds__(256) void pair_kernel(const float* __restrict__ b1,
                                                   const float* __restrict__ W2,
                                                   const float* __restrict__ b2) {
    __shared__ float hxs[JT * LOWER];
    __shared__ float red[256];

    const int tid = threadIdx.x;
    const int i   = blockIdx.y * IB + tid;
    const int j0  = blockIdx.x * JT;
    const float c = b2[0] - 1.0f;

    float a[LOWER], w[LOWER];
    #pragma unroll
    for (int u = 0; u < LOWER; u++) {
        a[u] = g_hy[i * LOWER + u] + b1[u];
        w[u] = W2[u];
    }

    #pragma unroll
    for (int idx = tid; idx < JT * LOWER; idx += 256)
        hxs[idx] = g_hx[j0 * LOWER + idx];
    __syncthreads();

    float s = 0.f;
    #pragma unroll 2
    for (int j = 0; j < JT; j++) {
        const float* hj = &hxs[j * LOWER];
        float t0 = c, t1 = 0.f;
        #pragma unroll
        for (int u = 0; u < LOWER; u += 2) {
            t0 = fmaf(w[u],     fmaxf(a[u]     + hj[u],     0.f), t0);
            t1 = fmaf(w[u + 1], fmaxf(a[u + 1] + hj[u + 1], 0.f), t1);
        }
        s += __expf(t0 + t1);
    }

    red[tid] = s;
    __syncthreads();
    for (int r2 = 128; r2 > 0; r2 >>= 1) {
        if (tid < r2) red[tid] += red[tid + r2];
        __syncthreads();
    }
    if (tid == 0) g_part_exp[blockIdx.y * NJB + blockIdx.x] = red[0];
}

// ---------------------------------------------------------------------------
// Kernel D: combine partials into the scalar lower bound.
// ---------------------------------------------------------------------------
__global__ void final_kernel(float* __restrict__ out) {
    int lane = threadIdx.x;  // 32 threads
    float t0 = 0.f, ex = 0.f;
    for (int k = lane; k < NT0B;  k += 32) t0 += g_part_t0[k];
    for (int k = lane; k < NPAIR; k += 32) ex += g_part_exp[k];
    #pragma unroll
    for (int off = 16; off; off >>= 1) {
        t0 += __shfl_xor_sync(0xFFFFFFFFu, t0, off);
        ex += __shfl_xor_sync(0xFFFFFFFFu, ex, off);
    }
    if (lane == 0)
        out[0] = t0 / (float)N_SAMPLES
               - ex / ((float)N_SAMPLES * (float)N_SAMPLES);
}

// ---------------------------------------------------------------------------
extern "C" void kernel_launch(void* const* d_in, const int* in_sizes, int n_in,
                              void* d_out, int out_size) {
    (void)in_sizes; (void)n_in; (void)out_size;
    const float* x  = (const float*)d_in[0];
    const float* y  = (const float*)d_in[1];
    const float* W1 = (const float*)d_in[2];
    const float* b1 = (const float*)d_in[3];
    const float* W2 = (const float*)d_in[4];
    const float* b2 = (const float*)d_in[5];
    float* out = (float*)d_out;

    h_gemm<<<dim3(N_SAMPLES / MT, 2), 128>>>(x, y, W1);
    t0_kernel<<<NT0B, 256>>>(b1, W2, b2);
    pair_kernel<<<dim3(NJB, NIB), 256>>>(b1, W2, b2);
    final_kernel<<<1, 32>>>(out);
}

// round 4
// speedup vs baseline: 1.2600x; 1.2600x over previous
#include <cuda_runtime.h>

#define N_SAMPLES 2048
#define XDIM      768
#define LOWER     40

// h-GEMM tiling
#define MT 32
#define KC 64
#define KPAD (KC + 4)    // float4-aligned row stride (272B), conflict-free

// pairwise tiling
#define JT  128                      // j per block (smem tile)
#define IB  256                      // i per block (1 per thread)
#define NJB (N_SAMPLES / JT)         // 16
#define NIB (N_SAMPLES / IB)         // 8
#define NPAIR (NJB * NIB)            // 128

__device__ float g_hx[N_SAMPLES * LOWER];
__device__ float g_hy[N_SAMPLES * LOWER];
__device__ float g_part_exp[NPAIR];

// ---- packed fp32x2 helpers (sm_100+: ptxas never auto-fuses these) ----
typedef unsigned long long u64p;
__device__ __forceinline__ u64p pk2(float lo, float hi) {
    u64p r; asm("mov.b64 %0, {%1, %2};" : "=l"(r) : "f"(lo), "f"(hi)); return r;
}
__device__ __forceinline__ void upk2(u64p v, float& lo, float& hi) {
    asm("mov.b64 {%0, %1}, %2;" : "=f"(lo), "=f"(hi) : "l"(v));
}
__device__ __forceinline__ u64p add2(u64p a, u64p b) {
    u64p r; asm("add.rn.f32x2 %0, %1, %2;" : "=l"(r) : "l"(a), "l"(b)); return r;
}
__device__ __forceinline__ u64p fma2(u64p a, u64p b, u64p c) {
    u64p r; asm("fma.rn.f32x2 %0, %1, %2, %3;" : "=l"(r) : "l"(a), "l"(b), "l"(c)); return r;
}
__device__ __forceinline__ u64p relu2(u64p v) {
    float lo, hi; upk2(v, lo, hi);
    return pk2(fmaxf(lo, 0.f), fmaxf(hi, 0.f));
}

// ---------------------------------------------------------------------------
// Kernel A: hx = x @ W1[:, :768]^T  and  hy = y @ W1[:, 768:]^T
// grid = (64, 2), block = 128. Each thread: 2 rows x 5 units, k packed x2.
// ---------------------------------------------------------------------------
__global__ __launch_bounds__(128) void h_gemm(const float* __restrict__ Xin,
                                              const float* __restrict__ Yin,
                                              const float* __restrict__ W1) {
    __shared__ float xs[MT][KPAD];
    __shared__ float ws[LOWER][KPAD];

    const float* X = blockIdx.y ? Yin : Xin;
    float* H       = blockIdx.y ? g_hy : g_hx;
    const int coloff = blockIdx.y ? XDIM : 0;

    const int tid  = threadIdx.x;
    const int row0 = blockIdx.x * MT;
    const int uu   = tid & 7;    // unit group: units [uu*5, uu*5+5)
    const int rr   = tid >> 3;   // rows rr and rr+16

    u64p acc0[5], acc1[5];
    #pragma unroll
    for (int jj = 0; jj < 5; jj++) { acc0[jj] = 0ull; acc1[jj] = 0ull; }

    for (int k0 = 0; k0 < XDIM; k0 += KC) {
        // x tile: 32 rows x 16 float4 = 512 float4 / 128 thr = 4 each
        #pragma unroll
        for (int q = 0; q < 4; q++) {
            int idx = tid + q * 128;          // 0..511
            int r = idx >> 4, kk4 = idx & 15; // 16 float4 per row
            *(float4*)&xs[r][kk4 * 4] =
                *(const float4*)&X[(row0 + r) * XDIM + k0 + kk4 * 4];
        }
        // w tile: 40 rows x 16 float4 = 640 / 128 = 5 each
        #pragma unroll
        for (int q = 0; q < 5; q++) {
            int idx = tid + q * 128;          // 0..639
            int u = idx >> 4, kk4 = idx & 15;
            *(float4*)&ws[u][kk4 * 4] =
                *(const float4*)&W1[u * (2 * XDIM) + coloff + k0 + kk4 * 4];
        }
        __syncthreads();

        #pragma unroll 4
        for (int kk = 0; kk < KC; kk += 2) {
            u64p xp0 = *(const u64p*)&xs[rr][kk];
            u64p xp1 = *(const u64p*)&xs[rr + 16][kk];
            #pragma unroll
            for (int jj = 0; jj < 5; jj++) {
                u64p wp = *(const u64p*)&ws[uu * 5 + jj][kk];
                acc0[jj] = fma2(xp0, wp, acc0[jj]);
                acc1[jj] = fma2(xp1, wp, acc1[jj]);
            }
        }
        __syncthreads();
    }

    #pragma unroll
    for (int jj = 0; jj < 5; jj++) {
        float l0, h0, l1, h1;
        upk2(acc0[jj], l0, h0); upk2(acc1[jj], l1, h1);
        H[(row0 + rr) * LOWER + uu * 5 + jj]      = l0 + h0;
        H[(row0 + rr + 16) * LOWER + uu * 5 + jj] = l1 + h1;
    }
}

// ---------------------------------------------------------------------------
// Kernel B: pairwise Sum_{i,j} exp( W2 . relu(hy_i + b1 + hx_j) + b2 - 1 )
// grid = (NJB, NIB), block = 256 (one i per thread), packed f32x2 math.
// ---------------------------------------------------------------------------
__global__ __launch_bounds__(256) void pair_kernel(const float* __restrict__ b1,
                                                   const float* __restrict__ W2,
                                                   const float* __restrict__ b2) {
    __shared__ float hxs[JT * LOWER];   // 20 KB
    __shared__ float red[256];

    const int tid = threadIdx.x;
    const int i   = blockIdx.y * IB + tid;
    const int j0  = blockIdx.x * JT;

    // a = hy_i + b1 (packed), w = W2 (packed)
    u64p a_p[20], w_p[20];
    {
        const float4* hy4 = (const float4*)&g_hy[i * LOWER];
        #pragma unroll
        for (int q = 0; q < 10; q++) {
            float4 h = hy4[q];
            float4 b = *(const float4*)&b1[4 * q];
            float4 w = *(const float4*)&W2[4 * q];
            a_p[2 * q]     = pk2(h.x + b.x, h.y + b.y);
            a_p[2 * q + 1] = pk2(h.z + b.z, h.w + b.w);
            w_p[2 * q]     = pk2(w.x, w.y);
            w_p[2 * q + 1] = pk2(w.z, w.w);
        }
    }

    // cooperative j-tile load: 1280 float4 / 256 thr = 5 each
    {
        const float4* src = (const float4*)&g_hx[j0 * LOWER];
        float4* dst = (float4*)hxs;
        #pragma unroll
        for (int q = 0; q < 5; q++) dst[tid + 256 * q] = src[tid + 256 * q];
    }
    __syncthreads();

    const float cm1 = b2[0] - 1.0f;
    float s = 0.f;

    #pragma unroll 2
    for (int j = 0; j < JT; j++) {
        const float4* hj4 = (const float4*)&hxs[j * LOWER];  // 160B offset: 16B aligned
        u64p acc0 = 0ull, acc1 = 0ull;   // bits(0,0) == (0.0f, 0.0f)
        #pragma unroll
        for (int q4 = 0; q4 < 10; q4++) {
            float4 hv = hj4[q4];
            u64p h01 = pk2(hv.x, hv.y);
            u64p h23 = pk2(hv.z, hv.w);
            u64p t0 = relu2(add2(a_p[2 * q4],     h01));
            u64p t1 = relu2(add2(a_p[2 * q4 + 1], h23));
            acc0 = fma2(t0, w_p[2 * q4],     acc0);
            acc1 = fma2(t1, w_p[2 * q4 + 1], acc1);
        }
        float al, ah, bl, bh;
        upk2(acc0, al, ah); upk2(acc1, bl, bh);
        s += __expf((al + bl) + (ah + bh) + cm1);
    }

    red[tid] = s;
    __syncthreads();
    for (int r2 = 128; r2 > 0; r2 >>= 1) {
        if (tid < r2) red[tid] += red[tid + r2];
        __syncthreads();
    }
    if (tid == 0) g_part_exp[blockIdx.y * NJB + blockIdx.x] = red[0];
}

// ---------------------------------------------------------------------------
// Kernel C: diagonal T0 term + final combine. One block, 256 threads.
// ---------------------------------------------------------------------------
__global__ __launch_bounds__(256) void final_kernel(const float* __restrict__ b1,
                                                    const float* __restrict__ W2,
                                                    const float* __restrict__ b2,
                                                    float* __restrict__ out) {
    __shared__ float red[256];
    const int tid = threadIdx.x;
    const float b2v = b2[0];

    float t = 0.f;
    for (int i = tid; i < N_SAMPLES; i += 256) {
        const float4* hx4 = (const float4*)&g_hx[i * LOWER];
        const float4* hy4 = (const float4*)&g_hy[i * LOWER];
        float acc = b2v;
        #pragma unroll
        for (int q = 0; q < 10; q++) {
            float4 x = hx4[q], y = hy4[q];
            float4 b = *(const float4*)&b1[4 * q];
            float4 w = *(const float4*)&W2[4 * q];
            acc = fmaf(w.x, fmaxf(x.x + y.x + b.x, 0.f), acc);
            acc = fmaf(w.y, fmaxf(x.y + y.y + b.y, 0.f), acc);
            acc = fmaf(w.z, fmaxf(x.z + y.z + b.z, 0.f), acc);
            acc = fmaf(w.w, fmaxf(x.w + y.w + b.w, 0.f), acc);
        }
        t += acc;
    }
    red[tid] = t;
    __syncthreads();
    for (int r2 = 128; r2 > 0; r2 >>= 1) {
        if (tid < r2) red[tid] += red[tid + r2];
        __syncthreads();
    }

    if (tid < 32) {
        float ex = 0.f;
        #pragma unroll
        for (int k = 0; k < NPAIR / 32; k++) ex += g_part_exp[tid + 32 * k];
        #pragma unroll
        for (int off = 16; off; off >>= 1)
            ex += __shfl_xor_sync(0xFFFFFFFFu, ex, off);
        if (tid == 0)
            out[0] = red[0] / (float)N_SAMPLES
                   - ex / ((float)N_SAMPLES * (float)N_SAMPLES);
    }
}

// ---------------------------------------------------------------------------
extern "C" void kernel_launch(void* const* d_in, const int* in_sizes, int n_in,
                              void* d_out, int out_size) {
    (void)in_sizes; (void)n_in; (void)out_size;
    const float* x  = (const float*)d_in[0];
    const float* y  = (const float*)d_in[1];
    const float* W1 = (const float*)d_in[2];
    const float* b1 = (const float*)d_in[3];
    const float* W2 = (const float*)d_in[4];
    const float* b2 = (const float*)d_in[5];
    float* out = (float*)d_out;

    h_gemm<<<dim3(N_SAMPLES / MT, 2), 128>>>(x, y, W1);
    pair_kernel<<<dim3(NJB, NIB), 256>>>(b1, W2, b2);
    final_kernel<<<1, 256>>>(b1, W2, b2, out);
}

// round 8
// speedup vs baseline: 1.5777x; 1.2521x over previous
#include <cuda_runtime.h>

#define N_SAMPLES 2048
#define XDIM      768
#define LOWER     40

// h-GEMM tiling
#define MT 32
#define KC 64
#define KPAD (KC + 4)    // float4-aligned row stride, conflict-free
#define KH  (XDIM / 2)   // K-split half: 384

// pairwise tiling
#define JT  64                       // j per block (smem tile)
#define IB  256                      // i per block (1 per thread)
#define NJB (N_SAMPLES / JT)         // 32
#define NIB (N_SAMPLES / IB)         // 8
#define NPAIR (NJB * NIB)            // 256

__device__ float g_hxA[N_SAMPLES * LOWER];
__device__ float g_hxB[N_SAMPLES * LOWER];
__device__ float g_hyA[N_SAMPLES * LOWER];
__device__ float g_hyB[N_SAMPLES * LOWER];
__device__ float g_part_exp[NPAIR];
__device__ float g_part_t0[NPAIR];

// ---- packed fp32x2 helpers ----
typedef unsigned long long u64p;
__device__ __forceinline__ u64p pk2(float lo, float hi) {
    u64p r; asm("mov.b64 %0, {%1, %2};" : "=l"(r) : "f"(lo), "f"(hi)); return r;
}
__device__ __forceinline__ void upk2(u64p v, float& lo, float& hi) {
    asm("mov.b64 {%0, %1}, %2;" : "=f"(lo), "=f"(hi) : "l"(v));
}
__device__ __forceinline__ u64p add2(u64p a, u64p b) {
    u64p r; asm("add.rn.f32x2 %0, %1, %2;" : "=l"(r) : "l"(a), "l"(b)); return r;
}
__device__ __forceinline__ u64p fma2(u64p a, u64p b, u64p c) {
    u64p r; asm("fma.rn.f32x2 %0, %1, %2, %3;" : "=l"(r) : "l"(a), "l"(b), "l"(c)); return r;
}
__device__ __forceinline__ u64p relu2(u64p v) {
    float lo, hi; upk2(v, lo, hi);
    return pk2(fmaxf(lo, 0.f), fmaxf(hi, 0.f));
}

// ---------------------------------------------------------------------------
// Kernel A: partial GEMMs. grid = (64, 2, 2): x = row tile, y = x/y side,
// z = K half. block = 256 (8 warps). Each thread: 1 row x 5 units.
// ---------------------------------------------------------------------------
__global__ __launch_bounds__(256) void h_gemm(const float* __restrict__ Xin,
                                              const float* __restrict__ Yin,
                                              const float* __restrict__ W1) {
    __shared__ float xs[MT][KPAD];
    __shared__ float ws[LOWER][KPAD];

    const float* X = blockIdx.y ? Yin : Xin;
    float* H = blockIdx.y ? (blockIdx.z ? g_hyB : g_hyA)
                          : (blockIdx.z ? g_hxB : g_hxA);
    const int coloff = (blockIdx.y ? XDIM : 0) + blockIdx.z * KH;
    const int kbase  = blockIdx.z * KH;

    const int tid  = threadIdx.x;
    const int row0 = blockIdx.x * MT;
    const int uu   = tid & 7;    // units [uu*5, uu*5+5)
    const int rr   = tid >> 3;   // row rr (0..31)

    u64p acc[5];
    #pragma unroll
    for (int jj = 0; jj < 5; jj++) acc[jj] = 0ull;

    for (int k0 = 0; k0 < KH; k0 += KC) {
        // x tile: 32 rows x 16 float4 = 512 / 256 thr = 2 each
        #pragma unroll
        for (int q = 0; q < 2; q++) {
            int idx = tid + q * 256;
            int r = idx >> 4, kk4 = idx & 15;
            *(float4*)&xs[r][kk4 * 4] =
                *(const float4*)&X[(row0 + r) * XDIM + kbase + k0 + kk4 * 4];
        }
        // w tile: 40 rows x 16 float4 = 640 / 256 thr = 3 each (guarded)
        #pragma unroll
        for (int q = 0; q < 3; q++) {
            int idx = tid + q * 256;
            if (idx < LOWER * 16) {
                int u = idx >> 4, kk4 = idx & 15;
                *(float4*)&ws[u][kk4 * 4] =
                    *(const float4*)&W1[u * (2 * XDIM) + coloff + k0 + kk4 * 4];
            }
        }
        __syncthreads();

        #pragma unroll 8
        for (int kk = 0; kk < KC; kk += 2) {
            u64p xp = *(const u64p*)&xs[rr][kk];
            #pragma unroll
            for (int jj = 0; jj < 5; jj++) {
                u64p wp = *(const u64p*)&ws[uu * 5 + jj][kk];
                acc[jj] = fma2(xp, wp, acc[jj]);
            }
        }
        __syncthreads();
    }

    #pragma unroll
    for (int jj = 0; jj < 5; jj++) {
        float lo, hi; upk2(acc[jj], lo, hi);
        H[(row0 + rr) * LOWER + uu * 5 + jj] = lo + hi;
    }
}

// ---------------------------------------------------------------------------
// Kernel B: pairwise Sum_{i,j} exp( W2 . relu(hy_i + b1 + hx_j) + b2 - 1 )
// plus the T0 diagonal term (computed by the block whose j-tile contains i).
// grid = (NJB, NIB) = (32, 8), block = 256 (one i per thread).
// ---------------------------------------------------------------------------
__global__ __launch_bounds__(256, 2) void pair_kernel(const float* __restrict__ b1,
                                                      const float* __restrict__ W2,
                                                      const float* __restrict__ b2) {
    __shared__ float hxs[JT * LOWER];   // 10 KB
    __shared__ float2 red[256];

    const int tid = threadIdx.x;
    const int i   = blockIdx.y * IB + tid;
    const int j0  = blockIdx.x * JT;
    const float b2v = b2[0];

    // a = hy_i + b1 (packed), w = W2 (packed)
    u64p a_p[20], w_p[20];
    {
        const float4* hyA4 = (const float4*)&g_hyA[i * LOWER];
        const float4* hyB4 = (const float4*)&g_hyB[i * LOWER];
        #pragma unroll
        for (int q = 0; q < 10; q++) {
            float4 ha = hyA4[q], hb = hyB4[q];
            float4 b = *(const float4*)&b1[4 * q];
            float4 w = *(const float4*)&W2[4 * q];
            a_p[2 * q]     = pk2(ha.x + hb.x + b.x, ha.y + hb.y + b.y);
            a_p[2 * q + 1] = pk2(ha.z + hb.z + b.z, ha.w + hb.w + b.w);
            w_p[2 * q]     = pk2(w.x, w.y);
            w_p[2 * q + 1] = pk2(w.z, w.w);
        }
    }

    // cooperative j-tile load: sum the two K-split partials. 640 float4.
    {
        const float4* A4 = (const float4*)&g_hxA[j0 * LOWER];
        const float4* B4 = (const float4*)&g_hxB[j0 * LOWER];
        float4* dst = (float4*)hxs;
        #pragma unroll
        for (int q = 0; q < 3; q++) {
            int idx = tid + 256 * q;
            if (idx < JT * LOWER / 4) {
                float4 a = A4[idx], b = B4[idx];
                float4 r; r.x = a.x + b.x; r.y = a.y + b.y;
                r.z = a.z + b.z; r.w = a.w + b.w;
                dst[idx] = r;
            }
        }
    }
    __syncthreads();

    const float cm1 = b2v - 1.0f;
    float s = 0.f;

    #pragma unroll 2
    for (int j = 0; j < JT; j++) {
        const u64p* hj = (const u64p*)&hxs[j * LOWER];
        u64p acc0 = 0ull, acc1 = 0ull;
        #pragma unroll
        for (int q = 0; q < 10; q++) {
            u64p t0 = relu2(add2(a_p[2 * q],     hj[2 * q]));
            u64p t1 = relu2(add2(a_p[2 * q + 1], hj[2 * q + 1]));
            acc0 = fma2(t0, w_p[2 * q],     acc0);
            acc1 = fma2(t1, w_p[2 * q + 1], acc1);
        }
        float al, ah, bl, bh;
        upk2(acc0, al, ah); upk2(acc1, bl, bh);
        s += __expf((al + bl) + (ah + bh) + cm1);
    }

    // T0 diagonal: this block owns hx_i in smem iff i is inside its j-tile.
    float tdiag = 0.f;
    {
        int li = i - j0;
        if (li >= 0 && li < JT) {
            float acc = b2v;
            #pragma unroll
            for (int q = 0; q < 20; q++) {
                float alo, ahi, wlo, whi;
                upk2(a_p[q], alo, ahi); upk2(w_p[q], wlo, whi);
                acc = fmaf(wlo, fmaxf(alo + hxs[li * LOWER + 2 * q],     0.f), acc);
                acc = fmaf(whi, fmaxf(ahi + hxs[li * LOWER + 2 * q + 1], 0.f), acc);
            }
            tdiag = acc;
        }
    }

    red[tid] = make_float2(s, tdiag);
    __syncthreads();
    for (int r2 = 128; r2 > 0; r2 >>= 1) {
        if (tid < r2) {
            float2 o = red[tid + r2];
            red[tid].x += o.x; red[tid].y += o.y;
        }
        __syncthreads();
    }
    if (tid == 0) {
        g_part_exp[blockIdx.y * NJB + blockIdx.x] = red[0].x;
        g_part_t0 [blockIdx.y * NJB + blockIdx.x] = red[0].y;
    }
}

// ---------------------------------------------------------------------------
// Kernel C: combine partials. 1 block, 32 threads.
// ---------------------------------------------------------------------------
__global__ void final_kernel(float* __restrict__ out) {
    int lane = threadIdx.x;
    float ex = 0.f, t0 = 0.f;
    #pragma unroll
    for (int k = 0; k < NPAIR / 32; k++) {
        ex += g_part_exp[lane + 32 * k];
        t0 += g_part_t0 [lane + 32 * k];
    }
    #pragma unroll
    for (int off = 16; off; off >>= 1) {
        ex += __shfl_xor_sync(0xFFFFFFFFu, ex, off);
        t0 += __shfl_xor_sync(0xFFFFFFFFu, t0, off);
    }
    if (lane == 0)
        out[0] = t0 / (float)N_SAMPLES
               - ex / ((float)N_SAMPLES * (float)N_SAMPLES);
}

// ---------------------------------------------------------------------------
extern "C" void kernel_launch(void* const* d_in, const int* in_sizes, int n_in,
                              void* d_out, int out_size) {
    (void)in_sizes; (void)n_in; (void)out_size;
    const float* x  = (const float*)d_in[0];
    const float* y  = (const float*)d_in[1];
    const float* W1 = (const float*)d_in[2];
    const float* b1 = (const float*)d_in[3];
    const float* W2 = (const float*)d_in[4];
    const float* b2 = (const float*)d_in[5];
    float* out = (float*)d_out;

    h_gemm<<<dim3(N_SAMPLES / MT, 2, 2), 256>>>(x, y, W1);
    pair_kernel<<<dim3(NJB, NIB), 256>>>(b1, W2, b2);
    final_kernel<<<1, 32>>>(out);
}

// round 12
// speedup vs baseline: 1.7306x; 1.0969x over previous
#include <cuda_runtime.h>

#define N_SAMPLES 2048
#define XDIM      768
#define LOWER     40

// h-GEMM tiling
#define MT    128                    // rows per block
#define KC    64                     // k per smem chunk
#define KPAD  (KC + 4)               // float4-aligned, conflict-friendly stride
#define SPLIT 4
#define KSEG  (XDIM / SPLIT)         // 192

// pairwise tiling
#define JT  64                       // j per block (smem tile)
#define IB  256                      // i per block (1 per thread)
#define NJB (N_SAMPLES / JT)         // 32
#define NIB (N_SAMPLES / IB)         // 8
#define NPAIR (NJB * NIB)            // 256

__device__ float g_hx[SPLIT][N_SAMPLES * LOWER];
__device__ float g_hy[SPLIT][N_SAMPLES * LOWER];
__device__ float g_part_exp[NPAIR];
__device__ float g_part_t0[NPAIR];

// ---- packed fp32x2 helpers ----
typedef unsigned long long u64p;
__device__ __forceinline__ u64p pk2(float lo, float hi) {
    u64p r; asm("mov.b64 %0, {%1, %2};" : "=l"(r) : "f"(lo), "f"(hi)); return r;
}
__device__ __forceinline__ void upk2(u64p v, float& lo, float& hi) {
    asm("mov.b64 {%0, %1}, %2;" : "=f"(lo), "=f"(hi) : "l"(v));
}
__device__ __forceinline__ u64p add2(u64p a, u64p b) {
    u64p r; asm("add.rn.f32x2 %0, %1, %2;" : "=l"(r) : "l"(a), "l"(b)); return r;
}
__device__ __forceinline__ u64p fma2(u64p a, u64p b, u64p c) {
    u64p r; asm("fma.rn.f32x2 %0, %1, %2, %3;" : "=l"(r) : "l"(a), "l"(b), "l"(c)); return r;
}
// relu on a packed pair: unpack, 2x FMNMX (alu pipe), repack. ptxas folds the
// movs into register pairing in most cases (no packed max exists in PTX).
__device__ __forceinline__ u64p relu2(u64p v) {
    float lo, hi; upk2(v, lo, hi);
    return pk2(fmaxf(lo, 0.f), fmaxf(hi, 0.f));
}

// ---------------------------------------------------------------------------
// Kernel A: partial GEMMs, register-blocked 4 rows x 5 units per thread.
// grid = (16, 2, 4): x = row tile, y = x/y side, z = K quarter. block = 256.
// ---------------------------------------------------------------------------
__global__ __launch_bounds__(256) void h_gemm(const float* __restrict__ Xin,
                                              const float* __restrict__ Yin,
                                              const float* __restrict__ W1) {
    __shared__ float xs[MT][KPAD];       // 34.8 KB
    __shared__ float ws[LOWER][KPAD];    // 10.9 KB

    const float* X = blockIdx.y ? Yin : Xin;
    float* H = blockIdx.y ? g_hy[blockIdx.z] : g_hx[blockIdx.z];
    const int coloff = (blockIdx.y ? XDIM : 0) + blockIdx.z * KSEG;
    const int kbase  = blockIdx.z * KSEG;

    const int tid  = threadIdx.x;
    const int row0 = blockIdx.x * MT;
    const int uu   = tid & 7;            // units [uu*5, uu*5+5)
    const int r0   = (tid >> 3) * 4;     // rows r0..r0+3

    u64p acc[4][5];
    #pragma unroll
    for (int r = 0; r < 4; r++)
        #pragma unroll
        for (int jj = 0; jj < 5; jj++) acc[r][jj] = 0ull;

    for (int k0 = 0; k0 < KSEG; k0 += KC) {
        // x tile: 128 rows x 16 float4 = 2048 / 256 thr = 8 each
        #pragma unroll
        for (int q = 0; q < 8; q++) {
            int idx = tid + q * 256;
            int r = idx >> 4, kk4 = idx & 15;
            *(float4*)&xs[r][kk4 * 4] =
                *(const float4*)&X[(row0 + r) * XDIM + kbase + k0 + kk4 * 4];
        }
        // w tile: 40 rows x 16 float4 = 640 / 256 thr = 3 each (guarded)
        #pragma unroll
        for (int q = 0; q < 3; q++) {
            int idx = tid + q * 256;
            if (idx < LOWER * 16) {
                int u = idx >> 4, kk4 = idx & 15;
                *(float4*)&ws[u][kk4 * 4] =
                    *(const float4*)&W1[u * (2 * XDIM) + coloff + k0 + kk4 * 4];
            }
        }
        __syncthreads();

        #pragma unroll 4
        for (int kk = 0; kk < KC; kk += 4) {
            ulonglong2 xv[4];
            #pragma unroll
            for (int r = 0; r < 4; r++)
                xv[r] = *(const ulonglong2*)&xs[r0 + r][kk];
            #pragma unroll
            for (int jj = 0; jj < 5; jj++) {
                ulonglong2 wv = *(const ulonglong2*)&ws[uu * 5 + jj][kk];
                #pragma unroll
                for (int r = 0; r < 4; r++) {
                    acc[r][jj] = fma2(xv[r].x, wv.x, acc[r][jj]);
                    acc[r][jj] = fma2(xv[r].y, wv.y, acc[r][jj]);
                }
            }
        }
        __syncthreads();
    }

    #pragma unroll
    for (int r = 0; r < 4; r++)
        #pragma unroll
        for (int jj = 0; jj < 5; jj++) {
            float lo, hi; upk2(acc[r][jj], lo, hi);
            H[(row0 + r0 + r) * LOWER + uu * 5 + jj] = lo + hi;
        }
}

// ---------------------------------------------------------------------------
// Kernel B: pairwise Sum_{i,j} exp( W2 . relu(hy_i + b1 + hx_j) + b2 - 1 )
// plus the T0 diagonal term. grid = (32, 8), block = 256 (one i per thread).
// ---------------------------------------------------------------------------
__global__ __launch_bounds__(256, 2) void pair_kernel(const float* __restrict__ b1,
                                                      const float* __restrict__ W2,
                                                      const float* __restrict__ b2) {
    __shared__ float hxs[JT * LOWER];   // 10 KB
    __shared__ float2 red[256];

    const int tid = threadIdx.x;
    const int i   = blockIdx.y * IB + tid;
    const int j0  = blockIdx.x * JT;
    const float b2v = b2[0];

    // a = sum_z hy_z[i] + b1 (packed), w = W2 (packed)
    u64p a_p[20], w_p[20];
    {
        const float4* h0 = (const float4*)&g_hy[0][i * LOWER];
        const float4* h1 = (const float4*)&g_hy[1][i * LOWER];
        const float4* h2 = (const float4*)&g_hy[2][i * LOWER];
        const float4* h3 = (const float4*)&g_hy[3][i * LOWER];
        #pragma unroll
        for (int q = 0; q < 10; q++) {
            float4 a = h0[q], b4 = h1[q], c = h2[q], d = h3[q];
            float4 bb = *(const float4*)&b1[4 * q];
            float4 w = *(const float4*)&W2[4 * q];
            a_p[2 * q]     = pk2(a.x + b4.x + c.x + d.x + bb.x,
                                 a.y + b4.y + c.y + d.y + bb.y);
            a_p[2 * q + 1] = pk2(a.z + b4.z + c.z + d.z + bb.z,
                                 a.w + b4.w + c.w + d.w + bb.w);
            w_p[2 * q]     = pk2(w.x, w.y);
            w_p[2 * q + 1] = pk2(w.z, w.w);
        }
    }

    // cooperative j-tile load: sum the 4 K-split partials. 640 float4.
    {
        const float4* A4 = (const float4*)&g_hx[0][j0 * LOWER];
        const float4* B4 = (const float4*)&g_hx[1][j0 * LOWER];
        const float4* C4 = (const float4*)&g_hx[2][j0 * LOWER];
        const float4* D4 = (const float4*)&g_hx[3][j0 * LOWER];
        float4* dst = (float4*)hxs;
        #pragma unroll
        for (int q = 0; q < 3; q++) {
            int idx = tid + 256 * q;
            if (idx < JT * LOWER / 4) {
                float4 a = A4[idx], b = B4[idx], c = C4[idx], d = D4[idx];
                float4 r;
                r.x = a.x + b.x + c.x + d.x;
                r.y = a.y + b.y + c.y + d.y;
                r.z = a.z + b.z + c.z + d.z;
                r.w = a.w + b.w + c.w + d.w;
                dst[idx] = r;
            }
        }
    }
    __syncthreads();

    const float cm1 = b2v - 1.0f;
    float s = 0.f;

    #pragma unroll 2
    for (int j = 0; j < JT; j++) {
        const ulonglong2* hj = (const ulonglong2*)&hxs[j * LOWER];  // 160B: aligned
        u64p acc0 = 0ull, acc1 = 0ull;
        #pragma unroll
        for (int q = 0; q < 10; q++) {
            ulonglong2 hv = hj[q];
            u64p t0 = relu2(add2(a_p[2 * q],     hv.x));
            u64p t1 = relu2(add2(a_p[2 * q + 1], hv.y));
            acc0 = fma2(t0, w_p[2 * q],     acc0);
            acc1 = fma2(t1, w_p[2 * q + 1], acc1);
        }
        float al, ah, bl, bh;
        upk2(acc0, al, ah); upk2(acc1, bl, bh);
        s += __expf((al + bl) + (ah + bh) + cm1);
    }

    // T0 diagonal: this block owns hx_i in smem iff i is inside its j-tile.
    float tdiag = 0.f;
    {
        int li = i - j0;
        if (li >= 0 && li < JT) {
            const ulonglong2* hi2 = (const ulonglong2*)&hxs[li * LOWER];
            u64p acc0 = 0ull, acc1 = 0ull;
            #pragma unroll
            for (int q = 0; q < 10; q++) {
                ulonglong2 hv = hi2[q];
                u64p t0 = relu2(add2(a_p[2 * q],     hv.x));
                u64p t1 = relu2(add2(a_p[2 * q + 1], hv.y));
                acc0 = fma2(t0, w_p[2 * q],     acc0);
                acc1 = fma2(t1, w_p[2 * q + 1], acc1);
            }
            float al, ah, bl, bh;
            upk2(acc0, al, ah); upk2(acc1, bl, bh);
            tdiag = (al + bl) + (ah + bh) + b2v;
        }
    }

    red[tid] = make_float2(s, tdiag);
    __syncthreads();
    for (int r2 = 128; r2 > 0; r2 >>= 1) {
        if (tid < r2) {
            float2 o = red[tid + r2];
            red[tid].x += o.x; red[tid].y += o.y;
        }
        __syncthreads();
    }
    if (tid == 0) {
        g_part_exp[blockIdx.y * NJB + blockIdx.x] = red[0].x;
        g_part_t0 [blockIdx.y * NJB + blockIdx.x] = red[0].y;
    }
}

// ---------------------------------------------------------------------------
// Kernel C: combine partials. 1 block, 32 threads.
// ---------------------------------------------------------------------------
__global__ void final_kernel(float* __restrict__ out) {
    int lane = threadIdx.x;
    float ex = 0.f, t0 = 0.f;
    #pragma unroll
    for (int k = 0; k < NPAIR / 32; k++) {
        ex += g_part_exp[lane + 32 * k];
        t0 += g_part_t0 [lane + 32 * k];
    }
    #pragma unroll
    for (int off = 16; off; off >>= 1) {
        ex += __shfl_xor_sync(0xFFFFFFFFu, ex, off);
        t0 += __shfl_xor_sync(0xFFFFFFFFu, t0, off);
    }
    if (lane == 0)
        out[0] = t0 / (float)N_SAMPLES
               - ex / ((float)N_SAMPLES * (float)N_SAMPLES);
}

// ---------------------------------------------------------------------------
extern "C" void kernel_launch(void* const* d_in, const int* in_sizes, int n_in,
                              void* d_out, int out_size) {
    (void)in_sizes; (void)n_in; (void)out_size;
    const float* x  = (const float*)d_in[0];
    const float* y  = (const float*)d_in[1];
    const float* W1 = (const float*)d_in[2];
    const float* b1 = (const float*)d_in[3];
    const float* W2 = (const float*)d_in[4];
    const float* b2 = (const float*)d_in[5];
    float* out = (float*)d_out;

    h_gemm<<<dim3(N_SAMPLES / MT, 2, SPLIT), 256>>>(x, y, W1);
    pair_kernel<<<dim3(NJB, NIB), 256>>>(b1, W2, b2);
    final_kernel<<<1, 32>>>(out);
}

// round 13
// speedup vs baseline: 1.8006x; 1.0405x over previous
#include <cuda_runtime.h>

#define N_SAMPLES 2048
#define XDIM      768
#define LOWER     40

// h-GEMM tiling
#define MT     64                    // rows per block
#define KC     48                    // k per smem chunk
#define KPAD   52                    // stride: %4==0 (float4) and conflict-free
#define SPLIT  4
#define KSEG   (XDIM / SPLIT)        // 192
#define NCHUNK (KSEG / KC)           // 4

// pairwise tiling
#define JT  64                       // j per block (smem tile)
#define IB  256                      // i per block (1 per thread)
#define NJB (N_SAMPLES / JT)         // 32
#define NIB (N_SAMPLES / IB)         // 8
#define NPAIR (NJB * NIB)            // 256

__device__ float g_hx[SPLIT][N_SAMPLES * LOWER];
__device__ float g_hy[SPLIT][N_SAMPLES * LOWER];
__device__ float g_hxs[N_SAMPLES * LOWER];     // merged hx
__device__ float g_hys[N_SAMPLES * LOWER];     // merged hy + b1
__device__ float g_part_exp[NPAIR];
__device__ float g_part_t0[NPAIR];

// ---- packed fp32x2 helpers ----
typedef unsigned long long u64p;
__device__ __forceinline__ u64p pk2(float lo, float hi) {
    u64p r; asm("mov.b64 %0, {%1, %2};" : "=l"(r) : "f"(lo), "f"(hi)); return r;
}
__device__ __forceinline__ void upk2(u64p v, float& lo, float& hi) {
    asm("mov.b64 {%0, %1}, %2;" : "=f"(lo), "=f"(hi) : "l"(v));
}
__device__ __forceinline__ u64p add2(u64p a, u64p b) {
    u64p r; asm("add.rn.f32x2 %0, %1, %2;" : "=l"(r) : "l"(a), "l"(b)); return r;
}
__device__ __forceinline__ u64p fma2(u64p a, u64p b, u64p c) {
    u64p r; asm("fma.rn.f32x2 %0, %1, %2, %3;" : "=l"(r) : "l"(a), "l"(b), "l"(c)); return r;
}
__device__ __forceinline__ u64p relu2(u64p v) {
    float lo, hi; upk2(v, lo, hi);
    return pk2(fmaxf(lo, 0.f), fmaxf(hi, 0.f));
}

// ---------------------------------------------------------------------------
// Kernel A: partial GEMMs, double-buffered smem, 2 rows x 5 units per thread.
// grid = (32, 2, 4): x = row tile, y = x/y side, z = K quarter. block = 256.
// ---------------------------------------------------------------------------
__global__ __launch_bounds__(256, 2) void h_gemm(const float* __restrict__ Xin,
                                                 const float* __restrict__ Yin,
                                                 const float* __restrict__ W1) {
    __shared__ float xs[2][MT][KPAD];       // 2 x 13.3 KB
    __shared__ float ws[2][LOWER][KPAD];    // 2 x 8.3 KB   (total 43.3 KB)

    const float* X = blockIdx.y ? Yin : Xin;
    float* H = blockIdx.y ? g_hy[blockIdx.z] : g_hx[blockIdx.z];
    const int coloff = (blockIdx.y ? XDIM : 0) + blockIdx.z * KSEG;
    const int kbase  = blockIdx.z * KSEG;

    const int tid  = threadIdx.x;
    const int row0 = blockIdx.x * MT;
    const int uu   = tid & 7;            // units [uu*5, uu*5+5)
    const int r0   = (tid >> 3) * 2;     // rows r0, r0+1

    u64p acc[2][5];
    #pragma unroll
    for (int r = 0; r < 2; r++)
        #pragma unroll
        for (int jj = 0; jj < 5; jj++) acc[r][jj] = 0ull;

    float4 rx[3], rw[2];

    // x tile: 64 rows x 12 float4 = 768 -> 3 per thread
    // w tile: 40 rows x 12 float4 = 480 -> 2 per thread (guarded)
    auto ldg = [&](int c) {
        #pragma unroll
        for (int q = 0; q < 3; q++) {
            int idx = tid + q * 256;
            int r = idx / 12, kk4 = idx % 12;
            rx[q] = *(const float4*)&X[(row0 + r) * XDIM + kbase + c * KC + kk4 * 4];
        }
        #pragma unroll
        for (int q = 0; q < 2; q++) {
            int idx = tid + q * 256;
            if (idx < 480) {
                int u = idx / 12, kk4 = idx % 12;
                rw[q] = *(const float4*)&W1[u * (2 * XDIM) + coloff + c * KC + kk4 * 4];
            }
        }
    };
    auto sts = [&](int b) {
        #pragma unroll
        for (int q = 0; q < 3; q++) {
            int idx = tid + q * 256;
            int r = idx / 12, kk4 = idx % 12;
            *(float4*)&xs[b][r][kk4 * 4] = rx[q];
        }
        #pragma unroll
        for (int q = 0; q < 2; q++) {
            int idx = tid + q * 256;
            if (idx < 480) {
                int u = idx / 12, kk4 = idx % 12;
                *(float4*)&ws[b][u][kk4 * 4] = rw[q];
            }
        }
    };

    ldg(0); sts(0); __syncthreads();

    #pragma unroll
    for (int c = 0; c < NCHUNK; c++) {
        const int cur = c & 1;
        if (c + 1 < NCHUNK) ldg(c + 1);

        #pragma unroll
        for (int kk = 0; kk < KC; kk += 4) {
            ulonglong2 xv0 = *(const ulonglong2*)&xs[cur][r0][kk];
            ulonglong2 xv1 = *(const ulonglong2*)&xs[cur][r0 + 1][kk];
            #pragma unroll
            for (int jj = 0; jj < 5; jj++) {
                ulonglong2 wv = *(const ulonglong2*)&ws[cur][uu * 5 + jj][kk];
                acc[0][jj] = fma2(xv0.x, wv.x, acc[0][jj]);
                acc[0][jj] = fma2(xv0.y, wv.y, acc[0][jj]);
                acc[1][jj] = fma2(xv1.x, wv.x, acc[1][jj]);
                acc[1][jj] = fma2(xv1.y, wv.y, acc[1][jj]);
            }
        }

        if (c + 1 < NCHUNK) { sts(cur ^ 1); __syncthreads(); }
    }

    #pragma unroll
    for (int r = 0; r < 2; r++)
        #pragma unroll
        for (int jj = 0; jj < 5; jj++) {
            float lo, hi; upk2(acc[r][jj], lo, hi);
            H[(row0 + r0 + r) * LOWER + uu * 5 + jj] = lo + hi;
        }
}

// ---------------------------------------------------------------------------
// Kernel A2: merge the 4 K-split partials once. hys also folds in +b1.
// 40960 float4 / 256 thr = 160 blocks.
// ---------------------------------------------------------------------------
__global__ __launch_bounds__(256) void merge_kernel(const float* __restrict__ b1) {
    const int idx = blockIdx.x * 256 + threadIdx.x;   // float4 index
    const bool isy = idx >= (N_SAMPLES * LOWER / 4);
    const int k = isy ? idx - (N_SAMPLES * LOWER / 4) : idx;

    const float4* A = (const float4*)(isy ? g_hy[0] : g_hx[0]);
    const float4* B = (const float4*)(isy ? g_hy[1] : g_hx[1]);
    const float4* C = (const float4*)(isy ? g_hy[2] : g_hx[2]);
    const float4* D = (const float4*)(isy ? g_hy[3] : g_hx[3]);

    float4 a = A[k], b = B[k], c = C[k], d = D[k];
    float4 r;
    r.x = a.x + b.x + c.x + d.x;
    r.y = a.y + b.y + c.y + d.y;
    r.z = a.z + b.z + c.z + d.z;
    r.w = a.w + b.w + c.w + d.w;
    if (isy) {
        float4 bb = *(const float4*)&b1[(k % (LOWER / 4)) * 4];
        r.x += bb.x; r.y += bb.y; r.z += bb.z; r.w += bb.w;
    }
    ((float4*)(isy ? g_hys : g_hxs))[k] = r;
}

// ---------------------------------------------------------------------------
// Kernel B: pairwise Sum_{i,j} exp( W2 . relu(hys_i + hxs_j) + b2 - 1 )
// plus the T0 diagonal term. grid = (32, 8), block = 256 (one i per thread).
// ---------------------------------------------------------------------------
__global__ __launch_bounds__(256, 2) void pair_kernel(const float* __restrict__ W2,
                                                      const float* __restrict__ b2) {
    __shared__ float hxs[JT * LOWER];   // 10 KB
    __shared__ float2 wred[8];

    const int tid  = threadIdx.x;
    const int lane = tid & 31;
    const int wid  = tid >> 5;
    const int i    = blockIdx.y * IB + tid;
    const int j0   = blockIdx.x * JT;
    const float b2v = b2[0];

    // a = hys_i (already includes b1), w = W2 (packed)
    u64p a_p[20], w_p[20];
    {
        const float4* hy4 = (const float4*)&g_hys[i * LOWER];
        #pragma unroll
        for (int q = 0; q < 10; q++) {
            float4 h = hy4[q];
            float4 w = *(const float4*)&W2[4 * q];
            a_p[2 * q]     = pk2(h.x, h.y);
            a_p[2 * q + 1] = pk2(h.z, h.w);
            w_p[2 * q]     = pk2(w.x, w.y);
            w_p[2 * q + 1] = pk2(w.z, w.w);
        }
    }

    // cooperative j-tile load: 640 float4 -> 3 per thread (guarded)
    {
        const float4* src = (const float4*)&g_hxs[j0 * LOWER];
        float4* dst = (float4*)hxs;
        #pragma unroll
        for (int q = 0; q < 3; q++) {
            int idx = tid + 256 * q;
            if (idx < JT * LOWER / 4) dst[idx] = src[idx];
        }
    }
    __syncthreads();

    const float cm1 = b2v - 1.0f;
    float s = 0.f;

    #pragma unroll 2
    for (int j = 0; j < JT; j++) {
        const ulonglong2* hj = (const ulonglong2*)&hxs[j * LOWER];  // 160B: aligned
        u64p acc0 = 0ull, acc1 = 0ull;
        #pragma unroll
        for (int q = 0; q < 10; q++) {
            ulonglong2 hv = hj[q];
            u64p t0 = relu2(add2(a_p[2 * q],     hv.x));
            u64p t1 = relu2(add2(a_p[2 * q + 1], hv.y));
            acc0 = fma2(t0, w_p[2 * q],     acc0);
            acc1 = fma2(t1, w_p[2 * q + 1], acc1);
        }
        float al, ah, bl, bh;
        upk2(acc0, al, ah); upk2(acc1, bl, bh);
        s += __expf((al + bl) + (ah + bh) + cm1);
    }

    // T0 diagonal: this block owns hxs_i in smem iff i is inside its j-tile.
    float tdiag = 0.f;
    {
        int li = i - j0;
        if (li >= 0 && li < JT) {
            const ulonglong2* hi2 = (const ulonglong2*)&hxs[li * LOWER];
            u64p acc0 = 0ull, acc1 = 0ull;
            #pragma unroll
            for (int q = 0; q < 10; q++) {
                ulonglong2 hv = hi2[q];
                u64p t0 = relu2(add2(a_p[2 * q],     hv.x));
                u64p t1 = relu2(add2(a_p[2 * q + 1], hv.y));
                acc0 = fma2(t0, w_p[2 * q],     acc0);
                acc1 = fma2(t1, w_p[2 * q + 1], acc1);
            }
            float al, ah, bl, bh;
            upk2(acc0, al, ah); upk2(acc1, bl, bh);
            tdiag = (al + bl) + (ah + bh) + b2v;
        }
    }

    // warp reduce, then cross-warp combine
    #pragma unroll
    for (int off = 16; off; off >>= 1) {
        s     += __shfl_xor_sync(0xFFFFFFFFu, s,     off);
        tdiag += __shfl_xor_sync(0xFFFFFFFFu, tdiag, off);
    }
    if (lane == 0) wred[wid] = make_float2(s, tdiag);
    __syncthreads();
    if (tid < 32) {
        float2 v = (tid < 8) ? wred[tid] : make_float2(0.f, 0.f);
        #pragma unroll
        for (int off = 4; off; off >>= 1) {
            v.x += __shfl_xor_sync(0xFFFFFFFFu, v.x, off);
            v.y += __shfl_xor_sync(0xFFFFFFFFu, v.y, off);
        }
        if (tid == 0) {
            g_part_exp[blockIdx.y * NJB + blockIdx.x] = v.x;
            g_part_t0 [blockIdx.y * NJB + blockIdx.x] = v.y;
        }
    }
}

// ---------------------------------------------------------------------------
// Kernel C: combine partials. 1 block, 32 threads.
// ---------------------------------------------------------------------------
__global__ void final_kernel(float* __restrict__ out) {
    int lane = threadIdx.x;
    float ex = 0.f, t0 = 0.f;
    #pragma unroll
    for (int k = 0; k < NPAIR / 32; k++) {
        ex += g_part_exp[lane + 32 * k];
        t0 += g_part_t0 [lane + 32 * k];
    }
    #pragma unroll
    for (int off = 16; off; off >>= 1) {
        ex += __shfl_xor_sync(0xFFFFFFFFu, ex, off);
        t0 += __shfl_xor_sync(0xFFFFFFFFu, t0, off);
    }
    if (lane == 0)
        out[0] = t0 / (float)N_SAMPLES
               - ex / ((float)N_SAMPLES * (float)N_SAMPLES);
}

// ---------------------------------------------------------------------------
extern "C" void kernel_launch(void* const* d_in, const int* in_sizes, int n_in,
                              void* d_out, int out_size) {
    (void)in_sizes; (void)n_in; (void)out_size;
    const float* x  = (const float*)d_in[0];
    const float* y  = (const float*)d_in[1];
    const float* W1 = (const float*)d_in[2];
    const float* b1 = (const float*)d_in[3];
    const float* W2 = (const float*)d_in[4];
    const float* b2 = (const float*)d_in[5];
    float* out = (float*)d_out;

    h_gemm<<<dim3(N_SAMPLES / MT, 2, SPLIT), 256>>>(x, y, W1);
    merge_kernel<<<2 * N_SAMPLES * LOWER / 4 / 256, 256>>>(b1);
    pair_kernel<<<dim3(NJB, NIB), 256>>>(W2, b2);
    final_kernel<<<1, 32>>>(out);
}